// round 7
// baseline (speedup 1.0000x reference)
#include <cuda_runtime.h>
#include <cstdint>

// ---------------------------------------------------------------------------
// GateMulti: out[b] = relu(x[b] @ W1[e] + b1[e]) @ W2[e] + b2[e],  e=groups[b,0]
// Round 6: persistent grouped tf32 GEMMs with dynamic tile stealing (296 CTAs),
// 3-stage cp.async pipeline, split-K=4 for GEMM2 + deterministic reduce.
// ---------------------------------------------------------------------------

namespace {
constexpr int NE    = 8;
constexpr int BATCH = 4096;
constexpr int DIN   = 512;
constexpr int DFF   = 2048;
constexpr int DOUT  = 512;

constexpr int BM = 128;
constexpr int BN = 128;
constexpr int BK = 32;
constexpr int STAGES = 3;
constexpr int SPLITK2 = 4;          // split-K factor for GEMM2
constexpr int MAX_TILES = 40;       // sum ceil(n_e/128) <= 4096/128 + 7 = 39
constexpr int NSM = 148;            // B200 SM count
constexpr int PERSIST_CTAS = 2 * NSM;

constexpr int ASTRIDE = 36;         // 36 % 32 == 4  -> conflict-free A frags
constexpr int BSTRIDE = 136;        // 136 % 32 == 8 -> conflict-free B frags
constexpr int A_ELEMS = BM * ASTRIDE;
constexpr int B_ELEMS = BK * BSTRIDE;
constexpr size_t SMEM_BYTES = (size_t)STAGES * (A_ELEMS + B_ELEMS) * sizeof(float);
}

// Scratch (device globals: no runtime allocation allowed)
__device__ int      g_perm[BATCH];
__device__ int      g_row_e[BATCH];                 // expert of perm position
__device__ int      g_tile_e[MAX_TILES];
__device__ int      g_tile_row0[MAX_TILES];
__device__ int      g_tile_rows[MAX_TILES];
__device__ int      g_ntiles;
__device__ unsigned g_ctr[2];                       // work-steal counters
__device__ float    g_H[(size_t)BATCH * DFF];       // hidden acts, perm order
__device__ float    g_Xr[(size_t)BATCH * DIN];      // x, tf32-rounded
__device__ float    g_P[(size_t)SPLITK2 * BATCH * DOUT];  // GEMM2 partials

__device__ __forceinline__ float tf32r(float f) {
    unsigned r;
    asm("cvt.rna.tf32.f32 %0, %1;" : "=r"(r) : "f"(f));
    return __uint_as_float(r);
}
__device__ __forceinline__ unsigned tf32r_bits(float f) {
    unsigned r;
    asm("cvt.rna.tf32.f32 %0, %1;" : "=r"(r) : "f"(f));
    return r;
}

__device__ __forceinline__ void cp16(float* dst_smem, const float* src) {
    unsigned d = (unsigned)__cvta_generic_to_shared(dst_smem);
    asm volatile("cp.async.cg.shared.global [%0], [%1], 16;\n" :: "r"(d), "l"(src));
}
__device__ __forceinline__ void cp_commit() {
    asm volatile("cp.async.commit_group;\n" ::: "memory");
}
template <int N>
__device__ __forceinline__ void cp_wait() {
    asm volatile("cp.async.wait_group %0;\n" :: "n"(N) : "memory");
}

__device__ __forceinline__ void mma8(float* c, const unsigned* a, const unsigned* b) {
    asm volatile(
        "mma.sync.aligned.m16n8k8.row.col.f32.tf32.tf32.f32 "
        "{%0,%1,%2,%3}, {%4,%5,%6,%7}, {%8,%9}, {%0,%1,%2,%3};"
        : "+f"(c[0]), "+f"(c[1]), "+f"(c[2]), "+f"(c[3])
        : "r"(a[0]), "r"(a[1]), "r"(a[2]), "r"(a[3]), "r"(b[0]), "r"(b[1]));
}

// ---------------------------------------------------------------------------
// Setup: bucket rows by expert (warp-aggregated atomics), build tile table,
// reset work-steal counters (runs before each GEMM pass on every replay).
// ---------------------------------------------------------------------------
__global__ void setup_kernel(const int* __restrict__ groups) {
    __shared__ int s_cnt[NE];
    __shared__ int s_cur[NE];
    const int tid  = threadIdx.x;
    const int lane = tid & 31;
    if (tid < NE) s_cnt[tid] = 0;
    if (tid == 0) { g_ctr[0] = 0; g_ctr[1] = 0; }
    __syncthreads();
    for (int i = tid; i < BATCH; i += blockDim.x) {
        const int e = groups[2 * i];
        const unsigned mask = __match_any_sync(0xffffffffu, e);
        if (lane == (__ffs(mask) - 1)) atomicAdd(&s_cnt[e], __popc(mask));
    }
    __syncthreads();
    if (tid == 0) {
        int base = 0, nt = 0;
        for (int e = 0; e < NE; e++) {
            s_cur[e] = base;
            const int c = s_cnt[e];
            for (int t0 = 0; t0 < c; t0 += BM) {
                g_tile_e[nt]    = e;
                g_tile_row0[nt] = base + t0;
                g_tile_rows[nt] = min(BM, c - t0);
                nt++;
            }
            base += c;
        }
        g_ntiles = nt;
    }
    __syncthreads();
    for (int i = tid; i < BATCH; i += blockDim.x) {
        const int e = groups[2 * i];
        const unsigned mask = __match_any_sync(0xffffffffu, e);
        const int leader = __ffs(mask) - 1;
        const int rank   = __popc(mask & ((1u << lane) - 1));
        int base = 0;
        if (lane == leader) base = atomicAdd(&s_cur[e], __popc(mask));
        base = __shfl_sync(0xffffffffu, base, leader);
        const int p = base + rank;
        g_perm[p]  = i;
        g_row_e[p] = e;
    }
}

// Pre-round x to tf32 (one float4 per thread).
__global__ void round_x_kernel(const float* __restrict__ x) {
    const int i = blockIdx.x * blockDim.x + threadIdx.x;
    float4 v = reinterpret_cast<const float4*>(x)[i];
    v.x = tf32r(v.x); v.y = tf32r(v.y); v.z = tf32r(v.z); v.w = tf32r(v.w);
    reinterpret_cast<float4*>(g_Xr)[i] = v;
}

// ---------------------------------------------------------------------------
// Persistent grouped GEMM, dynamic work stealing, 3-stage cp.async pipeline.
// PHASE 1: H = relu(gather(Xr) @ W1[e] + b1[e])       K=512,  N=2048
// PHASE 2: P[kz] = H @ W2[e]   (split-K=4, no bias)   K=512,  N=512
// 8 warps: 2(m) x 4(n), warp tile 64x32, m16n8k8 tf32.
// ---------------------------------------------------------------------------
template <int PHASE>
__global__ void __launch_bounds__(256, 2)
gemm_kernel(const float* __restrict__ Bg,
            const float* __restrict__ bias) {
    constexpr int Kd    = (PHASE == 1) ? DIN : DFF;
    constexpr int Nd    = (PHASE == 1) ? DFF : DOUT;
    constexpr int SPK   = (PHASE == 1) ? 1 : SPLITK2;
    constexpr int KLEN  = Kd / SPK;
    constexpr int NITER = KLEN / BK;
    constexpr int NT_N  = Nd / BN;

    extern __shared__ float smem[];
    float* AsBase = smem;                        // [STAGES][BM][ASTRIDE]
    float* BsBase = smem + STAGES * A_ELEMS;     // [STAGES][BK][BSTRIDE]
    __shared__ int s_src[BM];
    __shared__ int s_unit;

    const int nt = g_ntiles;
    const int U  = nt * NT_N * SPK;

    const int tid = threadIdx.x;
    const float* Aptr = (PHASE == 1) ? g_Xr : g_H;

    // loop-invariant thread mappings
    const int a_c = tid & 7,  a_r = tid >> 3;
    const int b_c = tid & 31, b_r = tid >> 5;
    const int warp = tid >> 5;
    const int lane = tid & 31;
    const int wm = warp & 1;          // 2 warps over M (64 rows each)
    const int wn = warp >> 1;         // 4 warps over N (32 cols each)
    const int g  = lane >> 2, tg = lane & 3;

    for (;;) {
        __syncthreads();   // prior unit: all smem reads done, s_unit consumed
        if (tid == 0) s_unit = atomicAdd(&g_ctr[PHASE - 1], 1u);
        __syncthreads();
        const int u = s_unit;
        if (u >= U) return;

        const int tile = u % nt;
        const int rem  = u / nt;
        const int n0   = (rem % NT_N) * BN;
        const int kz   = rem / NT_N;               // 0 for phase 1
        const int kt0  = kz * KLEN;

        const int e    = g_tile_e[tile];
        const int row0 = g_tile_row0[tile];
        const int rows = g_tile_rows[tile];

        if (tid < BM) {
            const int p = row0 + min(tid, rows - 1);  // clamp OOB rows
            s_src[tid] = (PHASE == 1) ? g_perm[p] : p;
        }
        __syncthreads();   // s_src ready; prior-unit stages safe to overwrite

        const float* Bbase = Bg + (size_t)e * Kd * Nd + n0;

        auto load_stage = [&](int kt, int s) {
            float* As = AsBase + s * A_ELEMS;
            float* Bs = BsBase + s * B_ELEMS;
            #pragma unroll
            for (int p = 0; p < 4; p++) {
                const int lr = a_r + p * 32;
                cp16(As + lr * ASTRIDE + a_c * 4,
                     Aptr + (size_t)s_src[lr] * Kd + kt + a_c * 4);
            }
            #pragma unroll
            for (int p = 0; p < 4; p++) {
                const int lr = b_r + p * 8;
                cp16(Bs + lr * BSTRIDE + b_c * 4,
                     Bbase + (size_t)(kt + lr) * Nd + b_c * 4);
            }
        };

        float acc[4][4][4];
        #pragma unroll
        for (int mi = 0; mi < 4; mi++)
            #pragma unroll
            for (int ni = 0; ni < 4; ni++)
                #pragma unroll
                for (int q = 0; q < 4; q++) acc[mi][ni][q] = 0.f;

        // prologue: prefetch STAGES-1 tiles
        #pragma unroll
        for (int s = 0; s < STAGES - 1; s++) {
            load_stage(kt0 + s * BK, s);
            cp_commit();
        }

        int smem_s = 0;
        for (int it = 0; it < NITER; it++) {
            cp_wait<STAGES - 2>();
            __syncthreads();   // compute stage landed; prev stage free

            const int it_next = it + (STAGES - 1);
            if (it_next < NITER) {
                const int s_next = (smem_s + STAGES - 1 < STAGES)
                                       ? smem_s + STAGES - 1
                                       : smem_s + STAGES - 1 - STAGES;
                load_stage(kt0 + it_next * BK, s_next);
            }
            cp_commit();   // commit every iter to keep group counts aligned

            const float* As = AsBase + smem_s * A_ELEMS;
            const float* Bs = BsBase + smem_s * B_ELEMS;

            #pragma unroll
            for (int kk = 0; kk < 4; kk++) {
                const int k0 = kk * 8;
                unsigned a[4][4], b[4][2];
                #pragma unroll
                for (int mi = 0; mi < 4; mi++) {
                    const int rb = wm * 64 + mi * 16;
                    a[mi][0] = __float_as_uint(As[(rb + g    ) * ASTRIDE + k0 + tg    ]);
                    a[mi][1] = __float_as_uint(As[(rb + g + 8) * ASTRIDE + k0 + tg    ]);
                    a[mi][2] = __float_as_uint(As[(rb + g    ) * ASTRIDE + k0 + tg + 4]);
                    a[mi][3] = __float_as_uint(As[(rb + g + 8) * ASTRIDE + k0 + tg + 4]);
                }
                #pragma unroll
                for (int ni = 0; ni < 4; ni++) {
                    const int cb = wn * 32 + ni * 8 + g;
                    b[ni][0] = tf32r_bits(Bs[(k0 + tg    ) * BSTRIDE + cb]);
                    b[ni][1] = tf32r_bits(Bs[(k0 + tg + 4) * BSTRIDE + cb]);
                }
                #pragma unroll
                for (int mi = 0; mi < 4; mi++)
                    #pragma unroll
                    for (int ni = 0; ni < 4; ni++)
                        mma8(acc[mi][ni], a[mi], b[ni]);
            }

            smem_s = (smem_s + 1 == STAGES) ? 0 : smem_s + 1;
        }

        // ---- epilogue (registers -> gmem; no smem stage reads) ----
        #pragma unroll
        for (int mi = 0; mi < 4; mi++) {
            #pragma unroll
            for (int ni = 0; ni < 4; ni++) {
                const int col = n0 + wn * 32 + ni * 8 + tg * 2;
                float2 bv = {0.f, 0.f};
                if (PHASE == 1)
                    bv = *reinterpret_cast<const float2*>(bias + (size_t)e * Nd + col);
                #pragma unroll
                for (int h = 0; h < 2; h++) {
                    const int lr = wm * 64 + mi * 16 + g + h * 8;
                    if (lr < rows) {
                        float v0 = acc[mi][ni][h * 2 + 0] + bv.x;
                        float v1 = acc[mi][ni][h * 2 + 1] + bv.y;
                        if (PHASE == 1) {
                            v0 = v0 > 0.f ? v0 : 0.f;
                            v1 = v1 > 0.f ? v1 : 0.f;
                            float2 o = {tf32r(v0), tf32r(v1)};  // pre-round for GEMM2
                            *reinterpret_cast<float2*>(
                                &g_H[(size_t)(row0 + lr) * DFF + col]) = o;
                        } else {
                            float2 o = {v0, v1};
                            *reinterpret_cast<float2*>(
                                &g_P[(size_t)kz * BATCH * DOUT +
                                     (size_t)(row0 + lr) * DOUT + col]) = o;
                        }
                    }
                }
            }
        }
    }
}

// ---------------------------------------------------------------------------
// Reduce: out[perm[r]] = sum_kz P[kz][r] + b2[e(r)].  Fixed order: determinstic.
// ---------------------------------------------------------------------------
__global__ void reduce_kernel(const float* __restrict__ b2,
                              float* __restrict__ outp) {
    const int i  = blockIdx.x * blockDim.x + threadIdx.x;   // over 4096*128 float4
    const int r  = i >> 7;
    const int c  = (i & 127) << 2;
    const int e  = g_row_e[r];
    float4 acc = *reinterpret_cast<const float4*>(&b2[(size_t)e * DOUT + c]);
    #pragma unroll
    for (int s = 0; s < SPLITK2; s++) {
        const float4 p = *reinterpret_cast<const float4*>(
            &g_P[(size_t)s * BATCH * DOUT + (size_t)r * DOUT + c]);
        acc.x += p.x; acc.y += p.y; acc.z += p.z; acc.w += p.w;
    }
    *reinterpret_cast<float4*>(&outp[(size_t)g_perm[r] * DOUT + c]) = acc;
}

// ---------------------------------------------------------------------------
// Launch graph-safe, allocation-free. Inputs: x, groups, W1, b1, W2, b2.
// ---------------------------------------------------------------------------
extern "C" void kernel_launch(void* const* d_in, const int* in_sizes, int n_in,
                              void* d_out, int out_size) {
    const float* x      = (const float*)d_in[0];
    const int*   groups = (const int*)  d_in[1];
    const float* W1     = (const float*)d_in[2];
    const float* b1     = (const float*)d_in[3];
    const float* W2     = (const float*)d_in[4];
    const float* b2     = (const float*)d_in[5];
    float*       out    = (float*)d_out;
    (void)in_sizes; (void)n_in; (void)out_size;

    cudaFuncSetAttribute(gemm_kernel<1>,
                         cudaFuncAttributeMaxDynamicSharedMemorySize, (int)SMEM_BYTES);
    cudaFuncSetAttribute(gemm_kernel<2>,
                         cudaFuncAttributeMaxDynamicSharedMemorySize, (int)SMEM_BYTES);

    setup_kernel<<<1, 256>>>(groups);
    round_x_kernel<<<(BATCH * DIN / 4) / 256, 256>>>(x);
    gemm_kernel<1><<<PERSIST_CTAS, 256, SMEM_BYTES>>>(W1, b1);
    gemm_kernel<2><<<PERSIST_CTAS, 256, SMEM_BYTES>>>(W2, nullptr);
    reduce_kernel<<<(BATCH * DOUT / 4) / 256, 256>>>(b2, out);
}

// round 9
// speedup vs baseline: 1.2521x; 1.2521x over previous
#include <cuda_runtime.h>
#include <cstdint>

// ---------------------------------------------------------------------------
// GateMulti: out[b] = relu(x[b] @ W1[e] + b1[e]) @ W2[e] + b2[e],  e=groups[b,0]
// Round 8: static grouped tf32 GEMMs, CTA tile 128x256, warp tile 64x64
// (halves smem bytes per MMA -> tensor-bound), 3-stage cp.async pipeline,
// 1 CTA/SM, split-K=4 for GEMM2 + deterministic reduce.
// ---------------------------------------------------------------------------

namespace {
constexpr int NE    = 8;
constexpr int BATCH = 4096;
constexpr int DIN   = 512;
constexpr int DFF   = 2048;
constexpr int DOUT  = 512;

constexpr int BM = 128;
constexpr int BN = 256;
constexpr int BK = 32;
constexpr int STAGES = 3;
constexpr int SPLITK2 = 4;          // split-K factor for GEMM2
constexpr int MAX_TILES = 40;       // sum ceil(n_e/128) <= 4096/128 + 7 = 39

constexpr int ASTRIDE = 36;         // 36 % 32 == 4  -> conflict-free A frags
constexpr int BSTRIDE = 264;        // 264 % 32 == 8 -> conflict-free B frags
constexpr int A_ELEMS = BM * ASTRIDE;
constexpr int B_ELEMS = BK * BSTRIDE;
constexpr size_t SMEM_BYTES = (size_t)STAGES * (A_ELEMS + B_ELEMS) * sizeof(float);
}

// Scratch (device globals: no runtime allocation allowed)
__device__ int   g_perm[BATCH];
__device__ int   g_row_e[BATCH];                    // expert of perm position
__device__ int   g_tile_e[MAX_TILES];
__device__ int   g_tile_row0[MAX_TILES];
__device__ int   g_tile_rows[MAX_TILES];
__device__ int   g_ntiles;
__device__ float g_H[(size_t)BATCH * DFF];          // hidden acts, perm order
__device__ float g_Xr[(size_t)BATCH * DIN];         // x, tf32-rounded
__device__ float g_P[(size_t)SPLITK2 * BATCH * DOUT];  // GEMM2 partials

__device__ __forceinline__ float tf32r(float f) {
    unsigned r;
    asm("cvt.rna.tf32.f32 %0, %1;" : "=r"(r) : "f"(f));
    return __uint_as_float(r);
}
__device__ __forceinline__ unsigned tf32r_bits(float f) {
    unsigned r;
    asm("cvt.rna.tf32.f32 %0, %1;" : "=r"(r) : "f"(f));
    return r;
}

__device__ __forceinline__ void cp16(float* dst_smem, const float* src) {
    unsigned d = (unsigned)__cvta_generic_to_shared(dst_smem);
    asm volatile("cp.async.cg.shared.global [%0], [%1], 16;\n" :: "r"(d), "l"(src));
}
__device__ __forceinline__ void cp_commit() {
    asm volatile("cp.async.commit_group;\n" ::: "memory");
}
template <int N>
__device__ __forceinline__ void cp_wait() {
    asm volatile("cp.async.wait_group %0;\n" :: "n"(N) : "memory");
}

__device__ __forceinline__ void mma8(float* c, const unsigned* a, const unsigned* b) {
    asm volatile(
        "mma.sync.aligned.m16n8k8.row.col.f32.tf32.tf32.f32 "
        "{%0,%1,%2,%3}, {%4,%5,%6,%7}, {%8,%9}, {%0,%1,%2,%3};"
        : "+f"(c[0]), "+f"(c[1]), "+f"(c[2]), "+f"(c[3])
        : "r"(a[0]), "r"(a[1]), "r"(a[2]), "r"(a[3]), "r"(b[0]), "r"(b[1]));
}

// ---------------------------------------------------------------------------
// Setup: bucket rows by expert (warp-aggregated atomics), build tile table.
// ---------------------------------------------------------------------------
__global__ void setup_kernel(const int* __restrict__ groups) {
    __shared__ int s_cnt[NE];
    __shared__ int s_cur[NE];
    const int tid  = threadIdx.x;
    const int lane = tid & 31;
    if (tid < NE) s_cnt[tid] = 0;
    __syncthreads();
    for (int i = tid; i < BATCH; i += blockDim.x) {
        const int e = groups[2 * i];
        const unsigned mask = __match_any_sync(0xffffffffu, e);
        if (lane == (__ffs(mask) - 1)) atomicAdd(&s_cnt[e], __popc(mask));
    }
    __syncthreads();
    if (tid == 0) {
        int base = 0, nt = 0;
        for (int e = 0; e < NE; e++) {
            s_cur[e] = base;
            const int c = s_cnt[e];
            for (int t0 = 0; t0 < c; t0 += BM) {
                g_tile_e[nt]    = e;
                g_tile_row0[nt] = base + t0;
                g_tile_rows[nt] = min(BM, c - t0);
                nt++;
            }
            base += c;
        }
        g_ntiles = nt;
    }
    __syncthreads();
    for (int i = tid; i < BATCH; i += blockDim.x) {
        const int e = groups[2 * i];
        const unsigned mask = __match_any_sync(0xffffffffu, e);
        const int leader = __ffs(mask) - 1;
        const int rank   = __popc(mask & ((1u << lane) - 1));
        int base = 0;
        if (lane == leader) base = atomicAdd(&s_cur[e], __popc(mask));
        base = __shfl_sync(0xffffffffu, base, leader);
        const int p = base + rank;
        g_perm[p]  = i;
        g_row_e[p] = e;
    }
}

// Pre-round x to tf32 (one float4 per thread).
__global__ void round_x_kernel(const float* __restrict__ x) {
    const int i = blockIdx.x * blockDim.x + threadIdx.x;
    float4 v = reinterpret_cast<const float4*>(x)[i];
    v.x = tf32r(v.x); v.y = tf32r(v.y); v.z = tf32r(v.z); v.w = tf32r(v.w);
    reinterpret_cast<float4*>(g_Xr)[i] = v;
}

// ---------------------------------------------------------------------------
// Grouped GEMM, 3-stage cp.async pipeline, single barrier per iteration.
// PHASE 1: H = relu(gather(Xr) @ W1[e] + b1[e])       K=512,  N=2048
// PHASE 2: P[kz] = H @ W2[e]   (split-K=4, no bias)   K=512,  N=512
// 8 warps: 2(m) x 4(n), warp tile 64x64, m16n8k8 tf32.
// ---------------------------------------------------------------------------
template <int PHASE>
__global__ void __launch_bounds__(256, 1)
gemm_kernel(const float* __restrict__ Bg,
            const float* __restrict__ bias) {
    constexpr int Kd    = (PHASE == 1) ? DIN : DFF;
    constexpr int Nd    = (PHASE == 1) ? DFF : DOUT;
    constexpr int SPK   = (PHASE == 1) ? 1 : SPLITK2;
    constexpr int KLEN  = Kd / SPK;
    constexpr int NITER = KLEN / BK;

    extern __shared__ float smem[];
    float* AsBase = smem;                        // [STAGES][BM][ASTRIDE]
    float* BsBase = smem + STAGES * A_ELEMS;     // [STAGES][BK][BSTRIDE]
    __shared__ int s_src[BM];

    const int tile = blockIdx.x;
    if (tile >= g_ntiles) return;
    const int e    = g_tile_e[tile];
    const int row0 = g_tile_row0[tile];
    const int rows = g_tile_rows[tile];
    const int n0   = blockIdx.y * BN;
    const int kz   = (PHASE == 2) ? blockIdx.z : 0;
    const int kt0  = kz * KLEN;

    const int tid = threadIdx.x;
    const float* Aptr = (PHASE == 1) ? g_Xr : g_H;

    if (tid < BM) {
        const int p = row0 + min(tid, rows - 1);   // clamp OOB rows to a valid one
        s_src[tid] = (PHASE == 1) ? g_perm[p] : p;
    }
    __syncthreads();

    const float* Bbase = Bg + (size_t)e * Kd * Nd + n0;

    // loader mapping: A = 32 rows x 8 float4-chunks per pass (4 passes),
    //                 B = 4 rows x 64 float4-chunks per pass (8 passes)
    const int a_c = tid & 7,  a_r = tid >> 3;
    const int b_c = tid & 63, b_r = tid >> 6;

    auto load_stage = [&](int kt, int s) {
        float* As = AsBase + s * A_ELEMS;
        float* Bs = BsBase + s * B_ELEMS;
        #pragma unroll
        for (int p = 0; p < 4; p++) {
            const int lr = a_r + p * 32;
            cp16(As + lr * ASTRIDE + a_c * 4,
                 Aptr + (size_t)s_src[lr] * Kd + kt + a_c * 4);
        }
        #pragma unroll
        for (int p = 0; p < 8; p++) {
            const int lr = b_r + p * 4;
            cp16(Bs + lr * BSTRIDE + b_c * 4,
                 Bbase + (size_t)(kt + lr) * Nd + b_c * 4);
        }
    };

    const int warp = tid >> 5;
    const int lane = tid & 31;
    const int wm = warp & 1;          // 2 warps over M (64 rows each)
    const int wn = warp >> 1;         // 4 warps over N (64 cols each)
    const int g  = lane >> 2, tg = lane & 3;

    float acc[4][8][4];
    #pragma unroll
    for (int mi = 0; mi < 4; mi++)
        #pragma unroll
        for (int ni = 0; ni < 8; ni++)
            #pragma unroll
            for (int q = 0; q < 4; q++) acc[mi][ni][q] = 0.f;

    // prologue: prefetch STAGES-1 tiles
    #pragma unroll
    for (int s = 0; s < STAGES - 1; s++) {
        load_stage(kt0 + s * BK, s);
        cp_commit();
    }

    int smem_s = 0;
    for (int it = 0; it < NITER; it++) {
        cp_wait<STAGES - 2>();
        __syncthreads();   // compute stage landed; prev stage free to refill

        const int it_next = it + (STAGES - 1);
        if (it_next < NITER) {
            const int s_next = (smem_s + STAGES - 1 < STAGES)
                                   ? smem_s + STAGES - 1
                                   : smem_s + STAGES - 1 - STAGES;
            load_stage(kt0 + it_next * BK, s_next);
        }
        cp_commit();    // commit every iter (possibly empty) to keep counts aligned

        const float* As = AsBase + smem_s * A_ELEMS;
        const float* Bs = BsBase + smem_s * B_ELEMS;

        #pragma unroll
        for (int kk = 0; kk < 4; kk++) {
            const int k0 = kk * 8;
            unsigned a[4][4], b[8][2];
            #pragma unroll
            for (int mi = 0; mi < 4; mi++) {
                const int rb = wm * 64 + mi * 16;
                a[mi][0] = __float_as_uint(As[(rb + g    ) * ASTRIDE + k0 + tg    ]);
                a[mi][1] = __float_as_uint(As[(rb + g + 8) * ASTRIDE + k0 + tg    ]);
                a[mi][2] = __float_as_uint(As[(rb + g    ) * ASTRIDE + k0 + tg + 4]);
                a[mi][3] = __float_as_uint(As[(rb + g + 8) * ASTRIDE + k0 + tg + 4]);
            }
            #pragma unroll
            for (int ni = 0; ni < 8; ni++) {
                const int cb = wn * 64 + ni * 8 + g;
                // weights arrive raw f32: rna-round in register
                b[ni][0] = tf32r_bits(Bs[(k0 + tg    ) * BSTRIDE + cb]);
                b[ni][1] = tf32r_bits(Bs[(k0 + tg + 4) * BSTRIDE + cb]);
            }
            #pragma unroll
            for (int mi = 0; mi < 4; mi++)
                #pragma unroll
                for (int ni = 0; ni < 8; ni++)
                    mma8(acc[mi][ni], a[mi], b[ni]);
        }

        smem_s = (smem_s + 1 == STAGES) ? 0 : smem_s + 1;
    }

    // ---- epilogue ----
    #pragma unroll
    for (int mi = 0; mi < 4; mi++) {
        #pragma unroll
        for (int ni = 0; ni < 8; ni++) {
            const int col = n0 + wn * 64 + ni * 8 + tg * 2;
            float2 bv = {0.f, 0.f};
            if (PHASE == 1)
                bv = *reinterpret_cast<const float2*>(bias + (size_t)e * Nd + col);
            #pragma unroll
            for (int h = 0; h < 2; h++) {
                const int lr = wm * 64 + mi * 16 + g + h * 8;
                if (lr < rows) {
                    float v0 = acc[mi][ni][h * 2 + 0] + bv.x;
                    float v1 = acc[mi][ni][h * 2 + 1] + bv.y;
                    if (PHASE == 1) {
                        v0 = v0 > 0.f ? v0 : 0.f;
                        v1 = v1 > 0.f ? v1 : 0.f;
                        float2 o = {tf32r(v0), tf32r(v1)};   // pre-round for GEMM2 A path
                        *reinterpret_cast<float2*>(
                            &g_H[(size_t)(row0 + lr) * DFF + col]) = o;
                    } else {
                        float2 o = {v0, v1};   // partial; bias added in reduce
                        *reinterpret_cast<float2*>(
                            &g_P[(size_t)kz * BATCH * DOUT +
                                 (size_t)(row0 + lr) * DOUT + col]) = o;
                    }
                }
            }
        }
    }
}

// ---------------------------------------------------------------------------
// Reduce: out[perm[r]] = sum_kz P[kz][r] + b2[e(r)].  Fixed order: deterministic.
// ---------------------------------------------------------------------------
__global__ void reduce_kernel(const float* __restrict__ b2,
                              float* __restrict__ outp) {
    const int i  = blockIdx.x * blockDim.x + threadIdx.x;   // over 4096*128 float4
    const int r  = i >> 7;
    const int c  = (i & 127) << 2;
    const int e  = g_row_e[r];
    float4 acc = *reinterpret_cast<const float4*>(&b2[(size_t)e * DOUT + c]);
    #pragma unroll
    for (int s = 0; s < SPLITK2; s++) {
        const float4 p = *reinterpret_cast<const float4*>(
            &g_P[(size_t)s * BATCH * DOUT + (size_t)r * DOUT + c]);
        acc.x += p.x; acc.y += p.y; acc.z += p.z; acc.w += p.w;
    }
    *reinterpret_cast<float4*>(&outp[(size_t)g_perm[r] * DOUT + c]) = acc;
}

// ---------------------------------------------------------------------------
// Launch graph-safe, allocation-free. Inputs: x, groups, W1, b1, W2, b2.
// ---------------------------------------------------------------------------
extern "C" void kernel_launch(void* const* d_in, const int* in_sizes, int n_in,
                              void* d_out, int out_size) {
    const float* x      = (const float*)d_in[0];
    const int*   groups = (const int*)  d_in[1];
    const float* W1     = (const float*)d_in[2];
    const float* b1     = (const float*)d_in[3];
    const float* W2     = (const float*)d_in[4];
    const float* b2     = (const float*)d_in[5];
    float*       out    = (float*)d_out;
    (void)in_sizes; (void)n_in; (void)out_size;

    cudaFuncSetAttribute(gemm_kernel<1>,
                         cudaFuncAttributeMaxDynamicSharedMemorySize, (int)SMEM_BYTES);
    cudaFuncSetAttribute(gemm_kernel<2>,
                         cudaFuncAttributeMaxDynamicSharedMemorySize, (int)SMEM_BYTES);

    setup_kernel<<<1, 256>>>(groups);
    round_x_kernel<<<(BATCH * DIN / 4) / 256, 256>>>(x);
    gemm_kernel<1><<<dim3(MAX_TILES, DFF / BN), 256, SMEM_BYTES>>>(W1, b1);
    gemm_kernel<2><<<dim3(MAX_TILES, DOUT / BN, SPLITK2), 256, SMEM_BYTES>>>(W2, nullptr);
    reduce_kernel<<<(BATCH * DOUT / 4) / 256, 256>>>(b2, out);
}

// round 12
// speedup vs baseline: 1.5632x; 1.2485x over previous
#include <cuda_runtime.h>
#include <cuda_fp16.h>
#include <cstdint>

// ---------------------------------------------------------------------------
// GateMulti: out[b] = relu(x[b] @ W1[e] + b1[e]) @ W2[e] + b2[e],  e=groups[b,0]
// Round 12: fp16 (m16n8k16, f32-accum) grouped GEMMs with ldmatrix fragment
// loads, 3-stage cp.async pipeline, 2 CTA/SM; split-K=2 GEMM2 + reduce.
// Fix vs r11: weight pointers selected in DEVICE code (never pass __device__
// globals as host-side kernel args).
// ---------------------------------------------------------------------------

namespace {
constexpr int NE    = 8;
constexpr int BATCH = 4096;
constexpr int DIN   = 512;
constexpr int DFF   = 2048;
constexpr int DOUT  = 512;

constexpr int BM = 128;
constexpr int BN = 128;
constexpr int BK = 32;              // halfs per K-tile
constexpr int STAGES = 3;
constexpr int SPLITK2 = 2;
constexpr int MAX_TILES = 40;

constexpr int ASTRIDE_H = 40;       // halfs; 80 B stride -> ldm conflict-free
constexpr int BSTRIDE_H = 136;      // halfs; 272 B stride -> ldm.trans conflict-free
constexpr int A_STAGE = BM * ASTRIDE_H * 2;   // 10240 B
constexpr int B_STAGE = BK * BSTRIDE_H * 2;   // 8704 B
constexpr int STAGE_BYTES = A_STAGE + B_STAGE;
constexpr size_t SMEM_BYTES = (size_t)STAGES * STAGE_BYTES;   // 56832 B
}

// Scratch (device globals; no runtime allocation allowed)
__device__ int   g_perm[BATCH];
__device__ int   g_row_e[BATCH];
__device__ int   g_tile_e[MAX_TILES];
__device__ int   g_tile_row0[MAX_TILES];
__device__ int   g_tile_rows[MAX_TILES];
__device__ int   g_ntiles;
__device__ __align__(16) __half g_Xh[(size_t)BATCH * DIN];
__device__ __align__(16) __half g_Hh[(size_t)BATCH * DFF];
__device__ __align__(16) __half g_W1h[(size_t)NE * DIN * DFF];
__device__ __align__(16) __half g_W2h[(size_t)NE * DFF * DOUT];
__device__ __align__(16) float  g_P[(size_t)SPLITK2 * BATCH * DOUT];

__device__ __forceinline__ void cp16s(unsigned dst, const void* src) {
    asm volatile("cp.async.cg.shared.global [%0], [%1], 16;" :: "r"(dst), "l"(src));
}
__device__ __forceinline__ void cp_commit() {
    asm volatile("cp.async.commit_group;" ::: "memory");
}
template <int N>
__device__ __forceinline__ void cp_wait() {
    asm volatile("cp.async.wait_group %0;" :: "n"(N) : "memory");
}

__device__ __forceinline__ void ldm4(unsigned* r, unsigned a) {
    asm volatile("ldmatrix.sync.aligned.m8n8.x4.shared.b16 {%0,%1,%2,%3}, [%4];"
                 : "=r"(r[0]), "=r"(r[1]), "=r"(r[2]), "=r"(r[3]) : "r"(a));
}
__device__ __forceinline__ void ldm4t(unsigned* r, unsigned a) {
    asm volatile("ldmatrix.sync.aligned.m8n8.x4.trans.shared.b16 {%0,%1,%2,%3}, [%4];"
                 : "=r"(r[0]), "=r"(r[1]), "=r"(r[2]), "=r"(r[3]) : "r"(a));
}

__device__ __forceinline__ void mma16(float* c, const unsigned* a,
                                      unsigned b0, unsigned b1) {
    asm volatile(
        "mma.sync.aligned.m16n8k16.row.col.f32.f16.f16.f32 "
        "{%0,%1,%2,%3}, {%4,%5,%6,%7}, {%8,%9}, {%0,%1,%2,%3};"
        : "+f"(c[0]), "+f"(c[1]), "+f"(c[2]), "+f"(c[3])
        : "r"(a[0]), "r"(a[1]), "r"(a[2]), "r"(a[3]), "r"(b0), "r"(b1));
}

// ---------------------------------------------------------------------------
// Setup: bucket rows by expert (warp-aggregated atomics), build tile table.
// ---------------------------------------------------------------------------
__global__ void setup_kernel(const int* __restrict__ groups) {
    __shared__ int s_cnt[NE];
    __shared__ int s_cur[NE];
    const int tid  = threadIdx.x;
    const int lane = tid & 31;
    if (tid < NE) s_cnt[tid] = 0;
    __syncthreads();
    for (int i = tid; i < BATCH; i += blockDim.x) {
        const int e = groups[2 * i];
        const unsigned mask = __match_any_sync(0xffffffffu, e);
        if (lane == (__ffs(mask) - 1)) atomicAdd(&s_cnt[e], __popc(mask));
    }
    __syncthreads();
    if (tid == 0) {
        int base = 0, nt = 0;
        for (int e = 0; e < NE; e++) {
            s_cur[e] = base;
            const int c = s_cnt[e];
            for (int t0 = 0; t0 < c; t0 += BM) {
                g_tile_e[nt]    = e;
                g_tile_row0[nt] = base + t0;
                g_tile_rows[nt] = min(BM, c - t0);
                nt++;
            }
            base += c;
        }
        g_ntiles = nt;
    }
    __syncthreads();
    for (int i = tid; i < BATCH; i += blockDim.x) {
        const int e = groups[2 * i];
        const unsigned mask = __match_any_sync(0xffffffffu, e);
        const int leader = __ffs(mask) - 1;
        const int rank   = __popc(mask & ((1u << lane) - 1));
        int base = 0;
        if (lane == leader) base = atomicAdd(&s_cur[e], __popc(mask));
        base = __shfl_sync(0xffffffffu, base, leader);
        const int p = base + rank;
        g_perm[p]  = i;
        g_row_e[p] = e;
    }
}

// ---------------------------------------------------------------------------
// f32 -> f16 conversion (rn). DST: 0 = g_Xh, 1 = g_W1h, 2 = g_W2h.
// ---------------------------------------------------------------------------
template <int DST>
__global__ void f2h_kernel(const float* __restrict__ in) {
    __half* out = (DST == 0) ? g_Xh : (DST == 1) ? g_W1h : g_W2h;
    const int i = blockIdx.x * blockDim.x + threadIdx.x;
    const float4 v = reinterpret_cast<const float4*>(in)[i];
    __half2* o2 = reinterpret_cast<__half2*>(out);
    o2[2 * i + 0] = __floats2half2_rn(v.x, v.y);
    o2[2 * i + 1] = __floats2half2_rn(v.z, v.w);
}

// ---------------------------------------------------------------------------
// fp16 grouped GEMM, 3-stage cp.async pipeline, one barrier per iteration.
// PHASE 1: H = relu(gather(Xh) @ W1h[e] + b1[e])      K=512,  N=2048
// PHASE 2: P[kz] = Hh @ W2h[e]  (split-K=2, no bias)  K=1024, N=512
// 8 warps: 2(m) x 4(n), warp tile 64x32, m16n8k16 f16/f32.
// ---------------------------------------------------------------------------
template <int PHASE>
__global__ void __launch_bounds__(256, 2)
gemm_kernel(const float* __restrict__ bias) {
    constexpr int Kd    = (PHASE == 1) ? DIN : DFF;
    constexpr int Nd    = (PHASE == 1) ? DFF : DOUT;
    constexpr int SPK   = (PHASE == 1) ? 1 : SPLITK2;
    constexpr int NITER = (Kd / SPK) / BK;

    extern __shared__ __align__(16) char smem_raw[];
    __shared__ int s_src[BM];

    const int tile = blockIdx.x;
    if (tile >= g_ntiles) return;
    const int e    = g_tile_e[tile];
    const int row0 = g_tile_row0[tile];
    const int rows = g_tile_rows[tile];
    const int n0   = blockIdx.y * BN;
    const int kz   = (PHASE == 2) ? blockIdx.z : 0;
    const int kt0  = kz * (Kd / SPK);

    const int tid = threadIdx.x;
    // DEVICE-side selection of device globals (r11 bug: was a host-side arg)
    const __half* Aptr = (PHASE == 1) ? g_Xh : g_Hh;
    const __half* Wptr = (PHASE == 1) ? g_W1h : g_W2h;

    if (tid < BM) {
        const int p = row0 + min(tid, rows - 1);   // clamp OOB rows
        s_src[tid] = (PHASE == 1) ? g_perm[p] : p;
    }
    __syncthreads();

    const __half* Bbase = Wptr + (size_t)e * Kd * Nd + n0;
    const unsigned sbase = (unsigned)__cvta_generic_to_shared(smem_raw);

    // stage loader: A 128 rows x 4 chunks(16B), B 32 rows x 16 chunks(16B);
    // 512 chunks each, 2 per thread.
    auto load_stage = [&](int kt, int s) {
        const unsigned Ast = sbase + s * STAGE_BYTES;
        const unsigned Bst = Ast + A_STAGE;
        #pragma unroll
        for (int p = 0; p < 2; p++) {
            const int ch = tid + p * 256;
            const int r = ch >> 2, j = ch & 3;
            cp16s(Ast + r * 80 + j * 16,
                  Aptr + (size_t)s_src[r] * Kd + kt + j * 8);
        }
        #pragma unroll
        for (int p = 0; p < 2; p++) {
            const int ch = tid + p * 256;
            const int r = ch >> 4, j = ch & 15;
            cp16s(Bst + r * 272 + j * 16,
                  Bbase + (size_t)(kt + r) * Nd + j * 8);
        }
    };

    const int warp = tid >> 5;
    const int lane = tid & 31;
    const int wm = warp & 1;          // 2 warps over M (64 rows)
    const int wn = warp >> 1;         // 4 warps over N (32 cols)
    const int g  = lane >> 2, tg = lane & 3;
    const int lr8 = lane & 7, lq = lane >> 3;

    // per-lane ldmatrix address offsets (bytes)
    const unsigned aoff = (unsigned)((lr8 + (lq & 1) * 8) * 80 + (lq >> 1) * 16);
    const unsigned boff = (unsigned)((lr8 + (lq >> 1) * 8) * 272 + (lq & 1) * 16);

    float acc[4][4][4];
    #pragma unroll
    for (int mi = 0; mi < 4; mi++)
        #pragma unroll
        for (int ni = 0; ni < 4; ni++)
            #pragma unroll
            for (int q = 0; q < 4; q++) acc[mi][ni][q] = 0.f;

    #pragma unroll
    for (int s = 0; s < STAGES - 1; s++) {
        load_stage(kt0 + s * BK, s);
        cp_commit();
    }

    int smem_s = 0;
    for (int it = 0; it < NITER; it++) {
        cp_wait<STAGES - 2>();
        __syncthreads();   // stage it%3 landed; stage (it-1)%3 reads done

        const int it_next = it + (STAGES - 1);
        if (it_next < NITER) {
            const int s_next = (smem_s + STAGES - 1 < STAGES)
                                   ? smem_s + STAGES - 1
                                   : smem_s + STAGES - 1 - STAGES;
            load_stage(kt0 + it_next * BK, s_next);
        }
        cp_commit();

        const unsigned Ast = sbase + smem_s * STAGE_BYTES;
        const unsigned Bst = Ast + A_STAGE;

        #pragma unroll
        for (int kk = 0; kk < 2; kk++) {       // 2 x k16 per BK=32
            const int k0 = kk * 16;
            unsigned a[4][4], bt[2][4];
            #pragma unroll
            for (int mi = 0; mi < 4; mi++)
                ldm4(a[mi], Ast + (wm * 64 + mi * 16) * 80 + aoff + k0 * 2);
            #pragma unroll
            for (int pr = 0; pr < 2; pr++)
                ldm4t(bt[pr], Bst + boff + k0 * 272 + (wn * 32 + pr * 16) * 2);
            #pragma unroll
            for (int mi = 0; mi < 4; mi++) {
                #pragma unroll
                for (int ni = 0; ni < 4; ni++) {
                    const int pr = ni >> 1, sel = ni & 1;
                    mma16(acc[mi][ni], a[mi], bt[pr][sel], bt[pr][sel + 2]);
                }
            }
        }

        smem_s = (smem_s + 1 == STAGES) ? 0 : smem_s + 1;
    }

    // ---- epilogue (same fragment mapping as m16n8 tf32) ----
    #pragma unroll
    for (int mi = 0; mi < 4; mi++) {
        #pragma unroll
        for (int ni = 0; ni < 4; ni++) {
            const int col = n0 + wn * 32 + ni * 8 + tg * 2;
            float2 bv = {0.f, 0.f};
            if (PHASE == 1)
                bv = *reinterpret_cast<const float2*>(bias + (size_t)e * Nd + col);
            #pragma unroll
            for (int h = 0; h < 2; h++) {
                const int lr = wm * 64 + mi * 16 + g + h * 8;
                if (lr < rows) {
                    float v0 = acc[mi][ni][h * 2 + 0] + bv.x;
                    float v1 = acc[mi][ni][h * 2 + 1] + bv.y;
                    if (PHASE == 1) {
                        v0 = v0 > 0.f ? v0 : 0.f;
                        v1 = v1 > 0.f ? v1 : 0.f;
                        *reinterpret_cast<__half2*>(
                            &g_Hh[(size_t)(row0 + lr) * DFF + col]) =
                            __floats2half2_rn(v0, v1);
                    } else {
                        float2 o = {v0, v1};   // partial; bias added in reduce
                        *reinterpret_cast<float2*>(
                            &g_P[(size_t)kz * BATCH * DOUT +
                                 (size_t)(row0 + lr) * DOUT + col]) = o;
                    }
                }
            }
        }
    }
}

// ---------------------------------------------------------------------------
// Reduce: out[perm[r]] = sum_kz P[kz][r] + b2[e(r)].  Fixed order: deterministic.
// ---------------------------------------------------------------------------
__global__ void reduce_kernel(const float* __restrict__ b2,
                              float* __restrict__ outp) {
    const int i = blockIdx.x * blockDim.x + threadIdx.x;
    const int r = i >> 7;
    const int c = (i & 127) << 2;
    const int e = g_row_e[r];
    float4 acc = *reinterpret_cast<const float4*>(&b2[(size_t)e * DOUT + c]);
    #pragma unroll
    for (int s = 0; s < SPLITK2; s++) {
        const float4 p = *reinterpret_cast<const float4*>(
            &g_P[(size_t)s * BATCH * DOUT + (size_t)r * DOUT + c]);
        acc.x += p.x; acc.y += p.y; acc.z += p.z; acc.w += p.w;
    }
    *reinterpret_cast<float4*>(&outp[(size_t)g_perm[r] * DOUT + c]) = acc;
}

// ---------------------------------------------------------------------------
// Launch: graph-safe, allocation-free. Inputs: x, groups, W1, b1, W2, b2.
// ---------------------------------------------------------------------------
extern "C" void kernel_launch(void* const* d_in, const int* in_sizes, int n_in,
                              void* d_out, int out_size) {
    const float* x      = (const float*)d_in[0];
    const int*   groups = (const int*)  d_in[1];
    const float* W1     = (const float*)d_in[2];
    const float* b1     = (const float*)d_in[3];
    const float* W2     = (const float*)d_in[4];
    const float* b2     = (const float*)d_in[5];
    float*       out    = (float*)d_out;
    (void)in_sizes; (void)n_in; (void)out_size;

    cudaFuncSetAttribute(gemm_kernel<1>,
                         cudaFuncAttributeMaxDynamicSharedMemorySize, (int)SMEM_BYTES);
    cudaFuncSetAttribute(gemm_kernel<2>,
                         cudaFuncAttributeMaxDynamicSharedMemorySize, (int)SMEM_BYTES);

    setup_kernel<<<1, 256>>>(groups);
    f2h_kernel<0><<<(BATCH * DIN / 4) / 256, 256>>>(x);
    f2h_kernel<1><<<(NE * DIN * DFF / 4) / 256, 256>>>(W1);
    f2h_kernel<2><<<(NE * DFF * DOUT / 4) / 256, 256>>>(W2);
    gemm_kernel<1><<<dim3(MAX_TILES, DFF / BN), 256, SMEM_BYTES>>>(b1);
    gemm_kernel<2><<<dim3(MAX_TILES, DOUT / BN, SPLITK2), 256, SMEM_BYTES>>>(nullptr);
    reduce_kernel<<<(BATCH * DOUT / 4) / 256, 256>>>(b2, out);
}